// round 1
// baseline (speedup 1.0000x reference)
#include <cuda_runtime.h>

// ---------------- problem constants ----------------
#define BB   8
#define TT   8
#define CC   32
#define HH   16
#define WW   28
#define HWp  (HH*WW)     // 448
#define NHh  4
#define DKk  8
#define RAD  3
#define NTHR_ATTN 224    // (8 y-rows) * 28 x
#define SS   8           // s-splits (one timestep per attention block)

// ---------------- device scratch (static; no cudaMalloc allowed) ----------------
__device__ float g_q   [BB*TT*CC*HWp];            // [bt][o=h*8+c][p], LN'd in place
__device__ float g_k   [BB*NHh*TT*DKk*HWp];       // [b][h][s][c][p]
__device__ float g_v   [BB*NHh*TT*DKk*HWp];
__device__ float g_tout[SS*BB*TT*NHh*DKk*HWp];    // partial attention outputs
__device__ float g_sum [SS*BB*TT*NHh*HWp];        // partial sum of exp2(a2-32)
__device__ float g_mx  [SS*BB*TT*NHh*HWp];        // partial max of (a2-32)

// fast exp2 via float round-trick + degree-4 Taylor; FMA-pipe only (no MUFU).
// valid for x <= ~30; clamps below -126 (returns ~2^-126, effectively 0 here).
__device__ __forceinline__ float exp2_fast(float x) {
    x = fmaxf(x, -126.0f);
    float z = __fadd_rn(x, 12582912.0f);          // 1.5*2^23 -> round to int
    float n = __fadd_rn(z, -12582912.0f);
    float f = x - n;                              // f in [-0.5, 0.5]
    int   sb = __float_as_int(z) * 8388608 + 0x3F800000;  // (n+127)<<23
    float p = fmaf(fmaf(fmaf(fmaf(0.0096181291f, f, 0.055504109f),
                             f, 0.24022651f), f, 0.69314718f), f, 1.0f);
    return p * __int_as_float(sb);
}

// ---------------- K1: Q/K/V projections ----------------
__global__ __launch_bounds__(256)
void k_proj(const float* __restrict__ first, const float* __restrict__ x,
            const float* __restrict__ Wq, const float* __restrict__ Wk,
            const float* __restrict__ Wv) {
    __shared__ float swq[1024], swk[1024], swv[1024];
    int tid = threadIdx.x;
    for (int i = tid; i < 1024; i += 256) { swq[i]=Wq[i]; swk[i]=Wk[i]; swv[i]=Wv[i]; }
    __syncthreads();

    int gi = blockIdx.x * 256 + tid;              // [0, B*T*HW) == 28672
    int p  = gi % HWp;
    int bt = gi / HWp;
    int b  = bt / TT, t = bt % TT;

    const float* fb = first + (size_t)bt * CC * HWp + p;
    const float* xb = x     + (size_t)bt * CC * HWp + p;
    float fv[CC], xv[CC];
    #pragma unroll
    for (int c = 0; c < CC; c++) { fv[c] = fb[c*HWp]; xv[c] = xb[c*HWp]; }

    #pragma unroll 4
    for (int o = 0; o < CC; o++) {
        float aq = 0.f, ak = 0.f, av = 0.f;
        #pragma unroll
        for (int c = 0; c < CC; c++) {
            aq = fmaf(fv[c], swq[o*CC+c], aq);
            ak = fmaf(xv[c], swk[o*CC+c], ak);
            av = fmaf(xv[c], swv[o*CC+c], av);
        }
        g_q[((size_t)bt*CC + o)*HWp + p] = aq;
        int h = o >> 3, c8 = o & 7;
        size_t kv = ((((size_t)b*NHh + h)*TT + t)*DKk + c8)*HWp + p;
        g_k[kv] = ak;
        g_v[kv] = av;
    }
}

// ---------------- K2: per-(b,t,head) LayerNorm of q ----------------
__global__ __launch_bounds__(128)
void k_ln(const float* __restrict__ gamma, const float* __restrict__ beta) {
    const int N = DKk * HWp;                      // 3584
    float* base = g_q + (size_t)blockIdx.x * N;   // blocks = B*T*NH = 256
    int tid = threadIdx.x;

    float vals[28];
    float s = 0.f, sq = 0.f;
    #pragma unroll
    for (int i = 0; i < 28; i++) {
        float v = base[tid + i*128];
        vals[i] = v; s += v; sq = fmaf(v, v, sq);
    }
    #pragma unroll
    for (int o = 16; o > 0; o >>= 1) {
        s  += __shfl_xor_sync(0xFFFFFFFFu, s,  o);
        sq += __shfl_xor_sync(0xFFFFFFFFu, sq, o);
    }
    __shared__ float shs[4], shq[4];
    if ((tid & 31) == 0) { shs[tid>>5] = s; shq[tid>>5] = sq; }
    __syncthreads();
    s  = shs[0]+shs[1]+shs[2]+shs[3];
    sq = shq[0]+shq[1]+shq[2]+shq[3];

    float mu   = s * (1.0f/3584.0f);
    float var  = fmaf(-mu, mu, sq * (1.0f/3584.0f));
    float rstd = rsqrtf(var + 1e-5f);
    #pragma unroll
    for (int i = 0; i < 28; i++) {
        int idx = tid + i*128;
        base[idx] = fmaf((vals[i]-mu)*rstd, gamma[idx], beta[idx]);
    }
}

// ---------------- K3: dilated local attention (per (b,head,s,t-half,y-half)) ----------------
__global__ __launch_bounds__(NTHR_ATTN, 2)
void k_attn() {
    // grid = 8b * 4head * 8s * 2ts * 2ys = 1024 blocks
    int bid = blockIdx.x;
    int ys   = bid & 1;  bid >>= 1;
    int ts   = bid & 1;  bid >>= 1;
    int s    = bid & 7;  bid >>= 3;
    int head = bid & 3;  bid >>= 2;
    int b    = bid;
    const int dil = 2*head + 1;                   // {1,3,5,7}

    __shared__ float sk[DKk*HWp];                 // 14336 B
    __shared__ float sv[DKk*HWp];

    int tid = threadIdx.x;
    {
        size_t kvbase = (((size_t)b*NHh + head)*TT + s) * DKk * HWp;
        const float* kg = g_k + kvbase;
        const float* vg = g_v + kvbase;
        for (int i = tid; i < DKk*HWp; i += NTHR_ATTN) { sk[i] = kg[i]; sv[i] = vg[i]; }
    }
    __syncthreads();

    int y = ys*8 + tid/WW;
    int xq = tid - (tid/WW)*WW;
    int t0 = ts*4;

    float qr[4][DKk];
    #pragma unroll
    for (int ti = 0; ti < 4; ti++) {
        const float* qb = g_q + (((size_t)(b*TT + t0+ti))*CC + head*DKk)*HWp + y*WW + xq;
        #pragma unroll
        for (int c = 0; c < DKk; c++) qr[ti][c] = qb[c*HWp];
    }

    float tout[4][DKk];
    float summ[4], mx[4];
    #pragma unroll
    for (int ti = 0; ti < 4; ti++) {
        summ[ti] = 0.f; mx[ti] = -1e30f;
        #pragma unroll
        for (int c = 0; c < DKk; c++) tout[ti][c] = 0.f;
    }

    const float INV_SCALE = 0.35355339059327373f;           // 1/sqrt(C/NH)
    const float S2 = 0.35355339059327373f * 1.4426950408889634f; // /scale * log2(e)

    #pragma unroll 1
    for (int oy = -RAD; oy <= RAD; oy++) {
        int yy = y + oy*dil;
        #pragma unroll 1
        for (int ox = -RAD; ox <= RAD; ox++) {
            int xx = xq + ox*dil;
            bool valid = ((unsigned)yy < HH) && ((unsigned)xx < WW);
            int ycl = min(max(yy, 0), HH-1);
            int xcl = min(max(xx, 0), WW-1);
            int sp  = ycl*WW + xcl;
            float ws  = valid ? INV_SCALE : 0.f;
            float s2v = valid ? S2 : 0.f;
            float bv  = valid ? -32.f : -160.f;   // -32 reference shift folded in

            float kv[DKk], vv[DKk];
            #pragma unroll
            for (int c = 0; c < DKk; c++) { kv[c] = sk[c*HWp + sp]; vv[c] = sv[c*HWp + sp]; }

            #pragma unroll
            for (int ti = 0; ti < 4; ti++) {
                float sc = 0.f;
                #pragma unroll
                for (int c = 0; c < DKk; c++) sc = fmaf(qr[ti][c], kv[c], sc);
                float w = sc * ws;
                #pragma unroll
                for (int c = 0; c < DKk; c++) tout[ti][c] = fmaf(w, vv[c], tout[ti][c]);
                float a2 = fmaf(sc, s2v, bv);     // shifted log2-score; -160 if masked
                mx[ti]   = fmaxf(mx[ti], a2);
                summ[ti] += exp2_fast(a2);
            }
        }
    }

    int p = y*WW + xq;
    #pragma unroll
    for (int ti = 0; ti < 4; ti++) {
        int bt = b*TT + (t0 + ti);
        size_t tb = ((((size_t)s*(BB*TT) + bt)*NHh + head)*DKk)*HWp + p;
        #pragma unroll
        for (int c = 0; c < DKk; c++) g_tout[tb + (size_t)c*HWp] = tout[ti][c];
        size_t mi = (((size_t)s*(BB*TT) + bt)*NHh + head)*HWp + p;
        g_sum[mi] = summ[ti];
        g_mx[mi]  = mx[ti];
    }
}

// ---------------- K4: combine partials, M_S, output projection ----------------
__global__ __launch_bounds__(256)
void k_out(const float* __restrict__ Wo, float* __restrict__ out) {
    __shared__ float swo[1024];
    int tid = threadIdx.x;
    for (int i = tid; i < 1024; i += 256) swo[i] = Wo[i];
    __syncthreads();

    int gi = blockIdx.x * 256 + tid;              // 28672
    int p  = gi % HWp;
    int bt = gi / HWp;

    float MS = 0.f;
    float tc[CC];
    #pragma unroll
    for (int h = 0; h < NHh; h++) {
        float s = 0.f, m = -1e30f;
        #pragma unroll
        for (int ssi = 0; ssi < SS; ssi++) {
            size_t mi = (((size_t)ssi*(BB*TT) + bt)*NHh + h)*HWp + p;
            s += g_sum[mi];
            m  = fmaxf(m, g_mx[mi]);
        }
        float Msh = exp2f(m) / s;                 // shifted consistently -> exact ratio
        MS = fmaxf(MS, Msh);
        #pragma unroll
        for (int c = 0; c < DKk; c++) {
            float acc = 0.f;
            #pragma unroll
            for (int ssi = 0; ssi < SS; ssi++)
                acc += g_tout[((((size_t)ssi*(BB*TT) + bt)*NHh + h)*DKk + c)*HWp + p];
            tc[h*DKk + c] = acc;
        }
    }

    float* ob = out + (size_t)bt * CC * HWp + p;
    #pragma unroll 4
    for (int o = 0; o < CC; o++) {
        float acc = 0.f;
        #pragma unroll
        for (int c = 0; c < CC; c++) acc = fmaf(tc[c], swo[o*CC + c], acc);
        ob[o*HWp] = acc * MS;
    }
}

// ---------------- launcher ----------------
extern "C" void kernel_launch(void* const* d_in, const int* in_sizes, int n_in,
                              void* d_out, int out_size) {
    const float* first = (const float*)d_in[0];
    const float* x     = (const float*)d_in[1];
    const float* Wq    = (const float*)d_in[2];
    const float* Wk    = (const float*)d_in[3];
    const float* Wv    = (const float*)d_in[4];
    const float* Wo    = (const float*)d_in[5];
    const float* lng   = (const float*)d_in[6];
    const float* lnb   = (const float*)d_in[7];
    float* out = (float*)d_out;

    k_proj<<<(BB*TT*HWp)/256, 256>>>(first, x, Wq, Wk, Wv);
    k_ln<<<BB*TT*NHh, 128>>>(lng, lnb);
    k_attn<<<BB*NHh*SS*2*2, NTHR_ATTN>>>();
    k_out<<<(BB*TT*HWp)/256, 256>>>(Wo, out);
}

// round 2
// speedup vs baseline: 1.1075x; 1.1075x over previous
#include <cuda_runtime.h>

typedef unsigned long long ull;

// ---------------- problem constants ----------------
#define BB   8
#define TT   8
#define CC   32
#define HH   16
#define WW   28
#define HWp  (HH*WW)     // 448
#define NHh  4
#define DKk  8
#define SG   2           // s-groups (each attention block loops 4 timesteps)

// ---------------- device scratch ----------------
__device__ __align__(16) float g_q   [BB*TT*CC*HWp];
__device__ __align__(16) float g_k   [BB*NHh*TT*DKk*HWp];       // [b][h][s][c][p]
__device__ __align__(16) float g_v   [BB*NHh*TT*DKk*HWp];
__device__ __align__(16) float g_tout[SG*BB*TT*HWp*NHh*DKk];    // [ss][bt][p][h*8+c]
__device__ __align__(16) float g_sum [SG*BB*TT*HWp*NHh];        // [ss][bt][p][h]
__device__ __align__(16) float g_mx  [SG*BB*TT*HWp*NHh];

// ---------------- packed f32x2 helpers (PTX-only; ptxas won't auto-fuse) ----------------
__device__ __forceinline__ ull pack2(float lo, float hi){ ull r; asm("mov.b64 %0,{%1,%2};":"=l"(r):"f"(lo),"f"(hi)); return r; }
__device__ __forceinline__ void unpack2(ull v, float& lo, float& hi){ asm("mov.b64 {%0,%1},%2;":"=f"(lo),"=f"(hi):"l"(v)); }
__device__ __forceinline__ ull pack2i(int lo, int hi){ ull r; asm("mov.b64 %0,{%1,%2};":"=l"(r):"r"(lo),"r"(hi)); return r; }
__device__ __forceinline__ void unpack2i(ull v, int& lo, int& hi){ asm("mov.b64 {%0,%1},%2;":"=r"(lo),"=r"(hi):"l"(v)); }
__device__ __forceinline__ ull fma2(ull a, ull b, ull c){ ull d; asm("fma.rn.f32x2 %0,%1,%2,%3;":"=l"(d):"l"(a),"l"(b),"l"(c)); return d; }
__device__ __forceinline__ ull add2(ull a, ull b){ ull d; asm("add.rn.f32x2 %0,%1,%2;":"=l"(d):"l"(a),"l"(b)); return d; }
__device__ __forceinline__ ull mul2(ull a, ull b){ ull d; asm("mul.rn.f32x2 %0,%1,%2;":"=l"(d):"l"(a),"l"(b)); return d; }

// scalar fast exp2 (round trick + deg-4 Taylor), FMA-pipe only
__device__ __forceinline__ float exp2_fast(float x) {
    float z = __fadd_rn(x, 12582912.0f);
    float n = __fadd_rn(z, -12582912.0f);
    float f = x - n;
    int   sb = __float_as_int(z) * 8388608 + 0x3F800000;
    float p = fmaf(fmaf(fmaf(fmaf(0.0096181291f, f, 0.055504109f),
                             f, 0.24022651f), f, 0.69314718f), f, 1.0f);
    return p * __int_as_float(sb);
}

// packed exp2 on both halves; inputs must be in [-126, ~30]
__device__ __forceinline__ ull exp2x2(ull x) {
    const ull C2  = pack2( 12582912.0f,  12582912.0f);
    const ull nC2 = pack2(-12582912.0f, -12582912.0f);
    const ull n1  = pack2(-1.0f, -1.0f);
    const ull c4  = pack2(0.0096181291f, 0.0096181291f);
    const ull c3  = pack2(0.055504109f,  0.055504109f);
    const ull c2  = pack2(0.24022651f,   0.24022651f);
    const ull c1  = pack2(0.69314718f,   0.69314718f);
    const ull one = pack2(1.0f, 1.0f);
    ull z = add2(x, C2);
    ull n = add2(z, nC2);
    ull f = fma2(n, n1, x);                         // x - n
    ull p = fma2(fma2(fma2(fma2(c4, f, c3), f, c2), f, c1), f, one);
    int zl, zh; unpack2i(z, zl, zh);
    int sl = zl * 8388608 + 0x3F800000;
    int sh = zh * 8388608 + 0x3F800000;
    return mul2(p, pack2i(sl, sh));
}

// ---------------- K1: Q/K/V projections (packed) ----------------
__global__ __launch_bounds__(128)
void k_proj(const float* __restrict__ first, const float* __restrict__ x,
            const float* __restrict__ Wq, const float* __restrict__ Wk,
            const float* __restrict__ Wv) {
    __shared__ float swq[1024], swk[1024], swv[1024];
    int tid = threadIdx.x;
    for (int i = tid; i < 1024; i += 128) { swq[i]=Wq[i]; swk[i]=Wk[i]; swv[i]=Wv[i]; }
    __syncthreads();

    int gi = blockIdx.x * 128 + tid;              // [0, 28672)
    int p  = gi % HWp;
    int bt = gi / HWp;
    int b  = bt >> 3, t = bt & 7;

    const float* fb = first + (size_t)bt * CC * HWp + p;
    const float* xb = x     + (size_t)bt * CC * HWp + p;
    ull fp[16], xp[16];
    #pragma unroll
    for (int j = 0; j < 16; j++) {
        fp[j] = pack2(fb[(2*j)*HWp], fb[(2*j+1)*HWp]);
        xp[j] = pack2(xb[(2*j)*HWp], xb[(2*j+1)*HWp]);
    }

    #pragma unroll 4
    for (int o = 0; o < CC; o++) {
        const ull* wq = (const ull*)&swq[o*CC];
        const ull* wk = (const ull*)&swk[o*CC];
        const ull* wv = (const ull*)&swv[o*CC];
        ull aq = mul2(fp[0], wq[0]);
        ull ak = mul2(xp[0], wk[0]);
        ull av = mul2(xp[0], wv[0]);
        #pragma unroll
        for (int j = 1; j < 16; j++) {
            aq = fma2(fp[j], wq[j], aq);
            ak = fma2(xp[j], wk[j], ak);
            av = fma2(xp[j], wv[j], av);
        }
        float l, h;
        unpack2(aq, l, h);
        g_q[((size_t)bt*CC + o)*HWp + p] = l + h;
        int hh = o >> 3, c8 = o & 7;
        size_t kv = ((((size_t)b*NHh + hh)*TT + t)*DKk + c8)*HWp + p;
        unpack2(ak, l, h); g_k[kv] = l + h;
        unpack2(av, l, h); g_v[kv] = l + h;
    }
}

// ---------------- K2: per-(b,t,head) LayerNorm of q ----------------
__global__ __launch_bounds__(128)
void k_ln(const float* __restrict__ gamma, const float* __restrict__ beta) {
    const int N = DKk * HWp;                      // 3584
    float* base = g_q + (size_t)blockIdx.x * N;   // blocks = B*T*NH = 256
    int tid = threadIdx.x;

    float vals[28];
    float s = 0.f, sq = 0.f;
    #pragma unroll
    for (int i = 0; i < 28; i++) {
        float v = base[tid + i*128];
        vals[i] = v; s += v; sq = fmaf(v, v, sq);
    }
    #pragma unroll
    for (int o = 16; o > 0; o >>= 1) {
        s  += __shfl_xor_sync(0xFFFFFFFFu, s,  o);
        sq += __shfl_xor_sync(0xFFFFFFFFu, sq, o);
    }
    __shared__ float shs[4], shq[4];
    if ((tid & 31) == 0) { shs[tid>>5] = s; shq[tid>>5] = sq; }
    __syncthreads();
    s  = shs[0]+shs[1]+shs[2]+shs[3];
    sq = shq[0]+shq[1]+shq[2]+shq[3];

    float mu   = s * (1.0f/3584.0f);
    float var  = fmaf(-mu, mu, sq * (1.0f/3584.0f));
    float rstd = rsqrtf(var + 1e-5f);
    #pragma unroll
    for (int i = 0; i < 28; i++) {
        int idx = tid + i*128;
        base[idx] = fmaf((vals[i]-mu)*rstd, gamma[idx], beta[idx]);
    }
}

// ---------------- K3: dilated local attention, t-packed f32x2, s-loop ----------------
__global__ __launch_bounds__(224, 2)
void k_attn() {
    // grid = 8b * 4head * 2sg * 2ts * 2ys = 256 blocks (single wave at occ 2)
    int bid = blockIdx.x;
    int ys   = bid & 1;  bid >>= 1;
    int ts   = bid & 1;  bid >>= 1;
    int sg   = bid & 1;  bid >>= 1;
    int head = bid & 3;  bid >>= 2;
    int b    = bid;
    const int dil = 2*head + 1;                   // {1,3,5,7}

    __shared__ float sk[DKk*HWp];                 // 14336 B
    __shared__ float sv[DKk*HWp];

    int tid = threadIdx.x;
    int y  = ys*8 + tid / WW;
    int xq = tid - (tid / WW) * WW;
    int t0 = ts*4;

    const float INV_SCALE = 0.35355339059327373f;                 // 1/sqrt(C/NH)
    const float S2C = 0.35355339059327373f * 1.4426950408889634f; // /scale * log2(e)

    // q packed over t-pairs: qp[pr][c] = (q[t0+2pr][c], q[t0+2pr+1][c])
    ull qp[2][DKk];
    #pragma unroll
    for (int c = 0; c < DKk; c++) {
        size_t qb = ((size_t)(b*TT + t0)*CC + head*DKk + c)*HWp + y*WW + xq;
        float q0 = g_q[qb];
        float q1 = g_q[qb +   (size_t)CC*HWp];
        float q2 = g_q[qb + 2*(size_t)CC*HWp];
        float q3 = g_q[qb + 3*(size_t)CC*HWp];
        qp[0][c] = pack2(q0, q1);
        qp[1][c] = pack2(q2, q3);
    }

    ull tout[2][DKk];
    ull summ[2];
    float mx[4];
    #pragma unroll
    for (int pr = 0; pr < 2; pr++) {
        summ[pr] = pack2(0.f, 0.f);
        #pragma unroll
        for (int c = 0; c < DKk; c++) tout[pr][c] = pack2(0.f, 0.f);
    }
    #pragma unroll
    for (int i = 0; i < 4; i++) mx[i] = -126.f;

    #pragma unroll 1
    for (int si = 0; si < 4; si++) {
        if (si) __syncthreads();
        {   // stage k/v for timestep s = sg*4+si
            size_t kb = (((size_t)(b*NHh + head)*TT) + (sg*4 + si)) * DKk * HWp;
            const float4* kg = (const float4*)(g_k + kb);
            const float4* vg = (const float4*)(g_v + kb);
            float4* sk4 = (float4*)sk;
            float4* sv4 = (float4*)sv;
            #pragma unroll
            for (int r = 0; r < 4; r++) {
                sk4[tid + r*224] = kg[tid + r*224];
                sv4[tid + r*224] = vg[tid + r*224];
            }
        }
        __syncthreads();

        #pragma unroll 1
        for (int oy = -3; oy <= 3; oy++) {
            int yy = y + oy*dil;
            if ((unsigned)yy >= (unsigned)HH) continue;   // warp-near-uniform row skip
            int rb = yy * WW;
            #pragma unroll 1
            for (int ox = -3; ox <= 3; ox++) {
                int xx = xq + ox*dil;
                bool vx = (unsigned)xx < (unsigned)WW;
                int sp = rb + (vx ? xx : 0);
                float wss = vx ? INV_SCALE : 0.f;
                float s2s = vx ? S2C : 0.f;
                float bvs = vx ? -32.f : -126.f;

                ull sc0, sc1;
                {
                    float kc = sk[sp];
                    ull kb2 = pack2(kc, kc);
                    sc0 = mul2(qp[0][0], kb2);
                    sc1 = mul2(qp[1][0], kb2);
                }
                #pragma unroll
                for (int c = 1; c < DKk; c++) {
                    float kc = sk[c*HWp + sp];
                    ull kb2 = pack2(kc, kc);
                    sc0 = fma2(qp[0][c], kb2, sc0);
                    sc1 = fma2(qp[1][c], kb2, sc1);
                }
                ull ws2 = pack2(wss, wss);
                ull w0 = mul2(sc0, ws2);
                ull w1 = mul2(sc1, ws2);
                #pragma unroll
                for (int c = 0; c < DKk; c++) {
                    float vc = sv[c*HWp + sp];
                    ull vb = pack2(vc, vc);
                    tout[0][c] = fma2(w0, vb, tout[0][c]);
                    tout[1][c] = fma2(w1, vb, tout[1][c]);
                }
                ull s22 = pack2(s2s, s2s);
                ull bv2 = pack2(bvs, bvs);
                ull a0 = fma2(sc0, s22, bv2);
                ull a1 = fma2(sc1, s22, bv2);
                float l, h;
                unpack2(a0, l, h); mx[0] = fmaxf(mx[0], l); mx[1] = fmaxf(mx[1], h);
                unpack2(a1, l, h); mx[2] = fmaxf(mx[2], l); mx[3] = fmaxf(mx[3], h);
                summ[0] = add2(summ[0], exp2x2(a0));
                summ[1] = add2(summ[1], exp2x2(a1));
            }
        }
    }

    // write partials: g_tout [ss][bt][p][h*8+c], g_sum/g_mx [ss][bt][p][h]
    int p = y*WW + xq;
    #pragma unroll
    for (int pr = 0; pr < 2; pr++) {
        float sl, sh; unpack2(summ[pr], sl, sh);
        float ea[DKk], eb[DKk];
        #pragma unroll
        for (int c = 0; c < DKk; c++) unpack2(tout[pr][c], ea[c], eb[c]);
        #pragma unroll
        for (int half = 0; half < 2; half++) {
            int t  = t0 + pr*2 + half;
            int bt = b*TT + t;
            float* tb = g_tout + ((size_t)(sg*(BB*TT) + bt)*HWp + p)*(NHh*DKk) + head*DKk;
            const float* src = half ? eb : ea;
            *(float4*)(tb)     = make_float4(src[0], src[1], src[2], src[3]);
            *(float4*)(tb + 4) = make_float4(src[4], src[5], src[6], src[7]);
            size_t mi = ((size_t)(sg*(BB*TT) + bt)*HWp + p)*NHh + head;
            g_sum[mi] = half ? sh : sl;
            g_mx[mi]  = mx[pr*2 + half];
        }
    }
}

// ---------------- K4: combine partials, M_S, output projection (packed) ----------------
__global__ __launch_bounds__(128)
void k_out(const float* __restrict__ Wo, float* __restrict__ out) {
    __shared__ float swo[1024];
    int tid = threadIdx.x;
    for (int i = tid; i < 1024; i += 128) swo[i] = Wo[i];
    __syncthreads();

    int gi = blockIdx.x * 128 + tid;              // [0, 28672)
    int p  = gi % HWp;
    int bt = gi / HWp;

    const float4* ta = (const float4*)(g_tout + ((size_t)bt*HWp + p)*(NHh*DKk));
    const float4* tb = (const float4*)(g_tout + ((size_t)(BB*TT + bt)*HWp + p)*(NHh*DKk));
    ull tc2[16];
    #pragma unroll
    for (int j = 0; j < 8; j++) {
        float4 u = ta[j], v = tb[j];
        tc2[2*j]   = pack2(u.x + v.x, u.y + v.y);
        tc2[2*j+1] = pack2(u.z + v.z, u.w + v.w);
    }

    float4 s0 = *(const float4*)(g_sum + ((size_t)bt*HWp + p)*NHh);
    float4 s1 = *(const float4*)(g_sum + ((size_t)(BB*TT + bt)*HWp + p)*NHh);
    float4 m0 = *(const float4*)(g_mx  + ((size_t)bt*HWp + p)*NHh);
    float4 m1 = *(const float4*)(g_mx  + ((size_t)(BB*TT + bt)*HWp + p)*NHh);

    float MS;
    {
        float sh0 = s0.x + s1.x, sh1 = s0.y + s1.y, sh2 = s0.z + s1.z, sh3 = s0.w + s1.w;
        float mh0 = fmaxf(m0.x, m1.x), mh1 = fmaxf(m0.y, m1.y);
        float mh2 = fmaxf(m0.z, m1.z), mh3 = fmaxf(m0.w, m1.w);
        MS =             __fdividef(exp2_fast(mh0), sh0);
        MS = fmaxf(MS,   __fdividef(exp2_fast(mh1), sh1));
        MS = fmaxf(MS,   __fdividef(exp2_fast(mh2), sh2));
        MS = fmaxf(MS,   __fdividef(exp2_fast(mh3), sh3));
    }

    float* ob = out + (size_t)bt * CC * HWp + p;
    #pragma unroll 4
    for (int o = 0; o < CC; o++) {
        const ull* wp = (const ull*)&swo[o*CC];
        ull acc = mul2(tc2[0], wp[0]);
        #pragma unroll
        for (int j = 1; j < 16; j++) acc = fma2(tc2[j], wp[j], acc);
        float l, h; unpack2(acc, l, h);
        ob[o*HWp] = (l + h) * MS;
    }
}

// ---------------- launcher ----------------
extern "C" void kernel_launch(void* const* d_in, const int* in_sizes, int n_in,
                              void* d_out, int out_size) {
    const float* first = (const float*)d_in[0];
    const float* x     = (const float*)d_in[1];
    const float* Wq    = (const float*)d_in[2];
    const float* Wk    = (const float*)d_in[3];
    const float* Wv    = (const float*)d_in[4];
    const float* Wo    = (const float*)d_in[5];
    const float* lng   = (const float*)d_in[6];
    const float* lnb   = (const float*)d_in[7];
    float* out = (float*)d_out;

    k_proj<<<224, 128>>>(first, x, Wq, Wk, Wv);
    k_ln<<<BB*TT*NHh, 128>>>(lng, lnb);
    k_attn<<<256, 224>>>();
    k_out<<<224, 128>>>(Wo, out);
}